// round 6
// baseline (speedup 1.0000x reference)
#include <cuda_runtime.h>

#define S 32
#define CCH 3
#define NSTEPS 4
#define DT_C 0.15f
#define EPS_C 1e-6f

// Precomputed Thomas factors: p = 1/denom, q = a/denom (== cstar since a==c).
// Layout: [step][channel][line][i] as float2.
__device__ float2 g_pqx[NSTEPS * CCH * S * S];
__device__ float2 g_pqy[NSTEPS * CCH * S * S];

__global__ void precompute_kernel(const float* __restrict__ alpha_base,
                                  const float* __restrict__ beta_base,
                                  const float* __restrict__ alpha_tc,
                                  const float* __restrict__ beta_tc) {
    int idx = blockIdx.x * blockDim.x + threadIdx.x;
    const int NLINES = NSTEPS * CCH * S;      // 384 per direction
    if (idx >= 2 * NLINES) return;
    int dir  = idx / NLINES;                  // 0 = x (solve along W), 1 = y (along H)
    int r    = idx % NLINES;
    int t    = r / (CCH * S);
    int c    = (r / S) % CCH;
    int line = r % S;                          // h for x-dir, w for y-dir

    float tv = (float)t * DT_C;
    const float* base = dir ? beta_base : alpha_base;
    const float* tc   = dir ? beta_tc   : alpha_tc;

    float raw[S];
    #pragma unroll
    for (int i = 0; i < S; i++) {
        int h = dir ? i : line;
        int w = dir ? line : i;
        int off = (c * S + h) * S + w;
        raw[i] = fmaxf(base[off] + tc[off] * tv, EPS_C);
    }
    // 3-tap replicate-padded smoothing along the solve dimension, times dt/DX^2
    float dt = dir ? DT_C : (DT_C * 0.5f);
    float cf[S];
    #pragma unroll
    for (int i = 0; i < S; i++) {
        float lm = raw[i == 0 ? 0 : i - 1];
        float rm = raw[i == S - 1 ? S - 1 : i + 1];
        cf[i] = (lm + raw[i] + rm) * (1.0f / 3.0f) * dt;
    }
    float2* out = dir ? g_pqy : g_pqx;
    long ob = ((long)(t * CCH + c) * S + line) * S;
    float cp = 0.0f;
    #pragma unroll
    for (int i = 0; i < S; i++) {
        float b = 1.0f + 2.0f * cf[i];
        if (i == 0 || i == S - 1) b = 1.0f + cf[i];
        float a = -cf[i];
        float denom = b - a * cp + EPS_C;     // matches reference (+EPS every step)
        float p = 1.0f / denom;
        float q = a * p;                      // also equals cstar_i (a == c)
        cp = q;
        out[ob + i] = make_float2(p, q);
    }
}

// One tridiagonal sweep of 32 independent systems (lane = batch) for one line.
// Coefficients come from a per-line smem table via *broadcast* LDS (all lanes
// read the same address -> 1 wavefront). asm volatile pins each load at its
// use site so ptxas cannot hoist 16 float4 live values and spill r[] (the R2
// failure mode). caddr = shared-space byte address of this line's float2[32].
template<bool COL, bool IN_SMEM, bool OUT_SMEM>
__device__ __forceinline__ void solve32(float* __restrict__ tile, float (&r)[S],
                                        unsigned caddr, int line, int lane,
                                        float scale) {
    float prev = 0.0f;
    #pragma unroll
    for (int i = 0; i < S; i++) {
        float p, q;
        asm volatile("ld.shared.v2.f32 {%0,%1},[%2];"
                     : "=f"(p), "=f"(q) : "r"(caddr + 8u * i));
        float d;
        if (IN_SMEM) {
            int e = COL ? (i * S + line) : (line * S + i);
            d = tile[e * 33 + lane];
        } else {
            d = r[i];
        }
        prev = fmaf(-q, prev, d * p);         // (d - a*prev)/denom
        r[i] = prev;
    }
    float x = r[S - 1];                       // cstar[N-1] irrelevant (x_N = 0)
    r[S - 1] = x * scale;
    if (OUT_SMEM) {
        int e = COL ? ((S - 1) * S + line) : (line * S + (S - 1));
        tile[e * 33 + lane] = x * scale;
    }
    #pragma unroll
    for (int i = S - 2; i >= 0; i--) {
        float q;                               // cstar_i == q_i
        asm volatile("ld.shared.f32 %0,[%1];"
                     : "=f"(q) : "r"(caddr + 8u * i + 4u));
        x = fmaf(-q, x, r[i]);
        r[i] = x * scale;
        if (OUT_SMEM) {
            int e = COL ? (i * S + line) : (line * S + i);
            tile[e * 33 + lane] = x * scale;
        }
    }
}

// Dynamic smem: [ scx2: 4096 float2 | scy2: 4096 float2 | tile: 33792 floats ]
#define COEF_F2_PER_DIR (NSTEPS * S * S)          // 4096 float2 = 32KB per dir
#define SMEM_BYTES (2 * COEF_F2_PER_DIR * 8 + S * S * 33 * 4)  // 200704 B

__global__ void __launch_bounds__(1024, 1)
adi_kernel(const float* __restrict__ U, const float* __restrict__ coupling,
           float* __restrict__ Out) {
    extern __shared__ float smem[];
    float2* scx2 = (float2*)smem;
    float2* scy2 = scx2 + COEF_F2_PER_DIR;
    float*  tile = (float*)(scy2 + COEF_F2_PER_DIR);

    int c    = blockIdx.x % CCH;
    int g    = blockIdx.x / CCH;
    int warp = threadIdx.x >> 5;
    int lane = threadIdx.x & 31;
    int tid  = threadIdx.x;

    // Stage this channel's (p,q) tables into smem (4 steps x 32 lines each dir).
    const float4* gx4 = (const float4*)g_pqx;
    const float4* gy4 = (const float4*)g_pqy;
    float4* sx4 = (float4*)scx2;
    float4* sy4 = (float4*)scy2;
    #pragma unroll
    for (int k = tid; k < NSTEPS * 512; k += 1024) {
        int t = k >> 9;                        // 512 float4 per step per dir
        int j = k & 511;
        sx4[t * 512 + j] = gx4[(t * CCH + c) * 512 + j];
        sy4[t * 512 + j] = gy4[(t * CCH + c) * 512 + j];
    }

    unsigned sbx = (unsigned)__cvta_generic_to_shared(scx2);
    unsigned sby = (unsigned)__cvta_generic_to_shared(scy2);

    size_t base = ((size_t)g * S) * (CCH * S * S) + (size_t)c * (S * S);
    const float* ub = U + base + (size_t)warp * (CCH * S * S);  // batch = g*32+warp

    // Coalesced load (128B/line) -> conflict-free STS thanks to the 33-pad.
    #pragma unroll
    for (int k = 0; k < S; k++)
        tile[(k * S + lane) * 33 + warp] = __ldg(ub + k * S + lane);

    float scal = coupling[c * CCH + c];       // einsum 'cc,bchw->bchw' = diag scale
    __syncthreads();

    float r[S];
    #pragma unroll 1
    for (int t = 0; t < NSTEPS; t++) {
        unsigned cax = sbx + (unsigned)((t * S + warp) * S) * 8u;
        unsigned cay = sby + (unsigned)((t * S + warp) * S) * 8u;

        // x half-step #1: rows. Input comes from registers for t>0 (fused with
        // previous step's x2 output, same warp/lane/addresses -> no barrier).
        if (t == 0) solve32<false, true,  true>(tile, r, cax, warp, lane, 1.0f);
        else        solve32<false, false, true>(tile, r, cax, warp, lane, 1.0f);
        __syncthreads();

        // y full step: columns (r reused as scratch; rows already flushed).
        solve32<true, true, true>(tile, r, cay, warp, lane, 1.0f);
        __syncthreads();

        // x half-step #2: rows, with channel coupling folded into the output.
        // For t<3 keep the result in registers only (next x1 consumes it).
        if (t == NSTEPS - 1) solve32<false, true, true >(tile, r, cax, warp, lane, scal);
        else                 solve32<false, true, false>(tile, r, cax, warp, lane, scal);
        if (t == NSTEPS - 1) __syncthreads();
    }

    float* ob = Out + base + (size_t)warp * (CCH * S * S);
    #pragma unroll
    for (int k = 0; k < S; k++)
        ob[k * S + lane] = tile[(k * S + lane) * 33 + warp];
}

extern "C" void kernel_launch(void* const* d_in, const int* in_sizes, int n_in,
                              void* d_out, int out_size) {
    (void)n_in; (void)out_size;
    const float* u   = (const float*)d_in[0];
    const float* ab  = (const float*)d_in[1];
    const float* bb  = (const float*)d_in[2];
    const float* atc = (const float*)d_in[3];
    const float* btc = (const float*)d_in[4];
    const float* cc  = (const float*)d_in[5];
    int B = in_sizes[0] / (CCH * S * S);      // 16384

    cudaFuncSetAttribute(adi_kernel, cudaFuncAttributeMaxDynamicSharedMemorySize,
                         SMEM_BYTES);

    precompute_kernel<<<3, 256>>>(ab, bb, atc, btc);   // 768 lines, trivial
    adi_kernel<<<(B / S) * CCH, 1024, SMEM_BYTES>>>(u, cc, (float*)d_out);
}

// round 7
// speedup vs baseline: 1.0141x; 1.0141x over previous
#include <cuda_runtime.h>

#define S 32
#define CCH 3
#define NSTEPS 4
#define DT_C 0.15f
#define EPS_C 1e-6f

// Precomputed Thomas factors: p = 1/denom, q = a/denom (== cstar since a==c).
// Layout: [step][channel][line][i] as float2.
__device__ float2 g_pqx[NSTEPS * CCH * S * S];
__device__ float2 g_pqy[NSTEPS * CCH * S * S];

__global__ void precompute_kernel(const float* __restrict__ alpha_base,
                                  const float* __restrict__ beta_base,
                                  const float* __restrict__ alpha_tc,
                                  const float* __restrict__ beta_tc) {
    int idx = blockIdx.x * blockDim.x + threadIdx.x;
    const int NLINES = NSTEPS * CCH * S;      // 384 per direction
    if (idx >= 2 * NLINES) return;
    int dir  = idx / NLINES;                  // 0 = x (solve along W), 1 = y (along H)
    int r    = idx % NLINES;
    int t    = r / (CCH * S);
    int c    = (r / S) % CCH;
    int line = r % S;                          // h for x-dir, w for y-dir

    float tv = (float)t * DT_C;
    const float* base = dir ? beta_base : alpha_base;
    const float* tc   = dir ? beta_tc   : alpha_tc;

    float raw[S];
    #pragma unroll
    for (int i = 0; i < S; i++) {
        int h = dir ? i : line;
        int w = dir ? line : i;
        int off = (c * S + h) * S + w;
        raw[i] = fmaxf(base[off] + tc[off] * tv, EPS_C);
    }
    // 3-tap replicate-padded smoothing along the solve dimension, times dt/DX^2
    float dt = dir ? DT_C : (DT_C * 0.5f);
    float cf[S];
    #pragma unroll
    for (int i = 0; i < S; i++) {
        float lm = raw[i == 0 ? 0 : i - 1];
        float rm = raw[i == S - 1 ? S - 1 : i + 1];
        cf[i] = (lm + raw[i] + rm) * (1.0f / 3.0f) * dt;
    }
    float2* out = dir ? g_pqy : g_pqx;
    long ob = ((long)(t * CCH + c) * S + line) * S;
    float cp = 0.0f;
    #pragma unroll
    for (int i = 0; i < S; i++) {
        float b = 1.0f + 2.0f * cf[i];
        if (i == 0 || i == S - 1) b = 1.0f + cf[i];
        float a = -cf[i];
        float denom = b - a * cp + EPS_C;     // matches reference (+EPS every step)
        float p = 1.0f / denom;
        float q = a * p;                      // also equals cstar_i (a == c)
        cp = q;
        out[ob + i] = make_float2(p, q);
    }
}

// One tridiagonal sweep of 32 independent systems (lane = batch) for one line.
// Coefficients come from a per-line smem table via *broadcast* LDS.128 (all
// lanes read the same 16B -> 1 wavefront delivering TWO (p,q) pairs, halving
// the broadcast slot count vs scalar). asm volatile pins each load at its use
// site so ptxas cannot hoist 16 vectors live and spill r[] (the R2 failure
// mode, proven fixed by pinning in R3). caddr = shared-space byte address of
// this line's float2[32] table (256B-aligned -> v4-safe).
template<bool COL, bool IN_SMEM, bool OUT_SMEM>
__device__ __forceinline__ void solve32(float* __restrict__ tile, float (&r)[S],
                                        unsigned caddr, int line, int lane,
                                        float scale) {
    float prev = 0.0f;
    #pragma unroll
    for (int j = 0; j < S / 2; j++) {
        float px0, qx0, px1, qx1;              // {p_2j, q_2j, p_2j+1, q_2j+1}
        asm volatile("ld.shared.v4.f32 {%0,%1,%2,%3},[%4];"
                     : "=f"(px0), "=f"(qx0), "=f"(px1), "=f"(qx1)
                     : "r"(caddr + 16u * j));
        int i0 = 2 * j;
        float d0;
        if (IN_SMEM) {
            int e = COL ? (i0 * S + line) : (line * S + i0);
            d0 = tile[e * 33 + lane];
        } else d0 = r[i0];
        prev = fmaf(-qx0, prev, d0 * px0);     // (d - a*prev)/denom
        r[i0] = prev;
        float d1;
        if (IN_SMEM) {
            int e = COL ? ((i0 + 1) * S + line) : (line * S + i0 + 1);
            d1 = tile[e * 33 + lane];
        } else d1 = r[i0 + 1];
        prev = fmaf(-qx1, prev, d1 * px1);
        r[i0 + 1] = prev;
    }
    float x = r[S - 1];                        // cstar[N-1] irrelevant (x_N = 0)
    r[S - 1] = x * scale;
    if (OUT_SMEM) {
        int e = COL ? ((S - 1) * S + line) : (line * S + (S - 1));
        tile[e * 33 + lane] = x * scale;
    }
    #pragma unroll
    for (int j = S / 2 - 1; j >= 0; j--) {
        float px0, qx0, px1, qx1;              // reuse pq v4: two q's per slot
        asm volatile("ld.shared.v4.f32 {%0,%1,%2,%3},[%4];"
                     : "=f"(px0), "=f"(qx0), "=f"(px1), "=f"(qx1)
                     : "r"(caddr + 16u * j));
        if (j < S / 2 - 1) {                   // i=31 already done (it's x itself)
            int i = 2 * j + 1;
            x = fmaf(-qx1, x, r[i]);           // cstar_i == q_i
            r[i] = x * scale;
            if (OUT_SMEM) {
                int e = COL ? (i * S + line) : (line * S + i);
                tile[e * 33 + lane] = x * scale;
            }
        }
        int i = 2 * j;
        x = fmaf(-qx0, x, r[i]);
        r[i] = x * scale;
        if (OUT_SMEM) {
            int e = COL ? (i * S + line) : (line * S + i);
            tile[e * 33 + lane] = x * scale;
        }
    }
}

// Dynamic smem: [ scx2: 4096 float2 | scy2: 4096 float2 | tile: 33792 floats ]
#define COEF_F2_PER_DIR (NSTEPS * S * S)          // 4096 float2 = 32KB per dir
#define SMEM_BYTES (2 * COEF_F2_PER_DIR * 8 + S * S * 33 * 4)  // 200704 B

__global__ void __launch_bounds__(1024, 1)
adi_kernel(const float* __restrict__ U, const float* __restrict__ coupling,
           float* __restrict__ Out) {
    extern __shared__ float smem[];
    float2* scx2 = (float2*)smem;
    float2* scy2 = scx2 + COEF_F2_PER_DIR;
    float*  tile = (float*)(scy2 + COEF_F2_PER_DIR);

    int c    = blockIdx.x % CCH;
    int g    = blockIdx.x / CCH;
    int warp = threadIdx.x >> 5;
    int lane = threadIdx.x & 31;
    int tid  = threadIdx.x;

    // Stage this channel's (p,q) tables into smem (4 steps x 32 lines each dir).
    const float4* gx4 = (const float4*)g_pqx;
    const float4* gy4 = (const float4*)g_pqy;
    float4* sx4 = (float4*)scx2;
    float4* sy4 = (float4*)scy2;
    #pragma unroll
    for (int k = tid; k < NSTEPS * 512; k += 1024) {
        int t = k >> 9;                        // 512 float4 per step per dir
        int j = k & 511;
        sx4[t * 512 + j] = gx4[(t * CCH + c) * 512 + j];
        sy4[t * 512 + j] = gy4[(t * CCH + c) * 512 + j];
    }

    unsigned sbx = (unsigned)__cvta_generic_to_shared(scx2);
    unsigned sby = (unsigned)__cvta_generic_to_shared(scy2);

    size_t base = ((size_t)g * S) * (CCH * S * S) + (size_t)c * (S * S);
    const float* ub = U + base + (size_t)warp * (CCH * S * S);  // batch = g*32+warp

    // Coalesced load (128B/line) -> conflict-free STS thanks to the 33-pad.
    #pragma unroll
    for (int k = 0; k < S; k++)
        tile[(k * S + lane) * 33 + warp] = __ldg(ub + k * S + lane);

    float scal = coupling[c * CCH + c];       // einsum 'cc,bchw->bchw' = diag scale
    __syncthreads();

    float r[S];
    #pragma unroll 1
    for (int t = 0; t < NSTEPS; t++) {
        unsigned cax = sbx + (unsigned)((t * S + warp) * S) * 8u;
        unsigned cay = sby + (unsigned)((t * S + warp) * S) * 8u;

        // x half-step #1: rows. Input comes from registers for t>0 (fused with
        // previous step's x2 output, same warp/lane/addresses -> no barrier).
        if (t == 0) solve32<false, true,  true>(tile, r, cax, warp, lane, 1.0f);
        else        solve32<false, false, true>(tile, r, cax, warp, lane, 1.0f);
        __syncthreads();

        // y full step: columns (r reused as scratch; rows already flushed).
        solve32<true, true, true>(tile, r, cay, warp, lane, 1.0f);
        __syncthreads();

        // x half-step #2: rows, with channel coupling folded into the output.
        // For t<3 keep the result in registers only (next x1 consumes it).
        if (t == NSTEPS - 1) solve32<false, true, true >(tile, r, cax, warp, lane, scal);
        else                 solve32<false, true, false>(tile, r, cax, warp, lane, scal);
        if (t == NSTEPS - 1) __syncthreads();
    }

    float* ob = Out + base + (size_t)warp * (CCH * S * S);
    #pragma unroll
    for (int k = 0; k < S; k++)
        ob[k * S + lane] = tile[(k * S + lane) * 33 + warp];
}

extern "C" void kernel_launch(void* const* d_in, const int* in_sizes, int n_in,
                              void* d_out, int out_size) {
    (void)n_in; (void)out_size;
    const float* u   = (const float*)d_in[0];
    const float* ab  = (const float*)d_in[1];
    const float* bb  = (const float*)d_in[2];
    const float* atc = (const float*)d_in[3];
    const float* btc = (const float*)d_in[4];
    const float* cc  = (const float*)d_in[5];
    int B = in_sizes[0] / (CCH * S * S);      // 16384

    cudaFuncSetAttribute(adi_kernel, cudaFuncAttributeMaxDynamicSharedMemorySize,
                         SMEM_BYTES);

    precompute_kernel<<<3, 256>>>(ab, bb, atc, btc);   // 768 lines, trivial
    adi_kernel<<<(B / S) * CCH, 1024, SMEM_BYTES>>>(u, cc, (float*)d_out);
}

// round 8
// speedup vs baseline: 1.1306x; 1.1149x over previous
#include <cuda_runtime.h>

#define S 32
#define CCH 3
#define NSTEPS 4
#define DT_C 0.15f
#define EPS_C 1e-6f

// Precomputed Thomas factors, de-interleaved: p = 1/denom, q = a/denom
// (== cstar since a==c). Packed per line as float[32] so one v4 broadcast
// delivers 4 consecutive p's (or q's): fwd needs p+q (16 loads), bwd needs
// only q (8 loads) -> 24 broadcast wavefronts/solve vs 32 interleaved.
__device__ float g_px[NSTEPS * CCH * S * S];
__device__ float g_qx[NSTEPS * CCH * S * S];
__device__ float g_py[NSTEPS * CCH * S * S];
__device__ float g_qy[NSTEPS * CCH * S * S];

__global__ void precompute_kernel(const float* __restrict__ alpha_base,
                                  const float* __restrict__ beta_base,
                                  const float* __restrict__ alpha_tc,
                                  const float* __restrict__ beta_tc) {
    int idx = blockIdx.x * blockDim.x + threadIdx.x;
    const int NLINES = NSTEPS * CCH * S;      // 384 per direction
    if (idx >= 2 * NLINES) return;
    int dir  = idx / NLINES;                  // 0 = x (solve along W), 1 = y (along H)
    int r    = idx % NLINES;
    int t    = r / (CCH * S);
    int c    = (r / S) % CCH;
    int line = r % S;                          // h for x-dir, w for y-dir

    float tv = (float)t * DT_C;
    const float* base = dir ? beta_base : alpha_base;
    const float* tc   = dir ? beta_tc   : alpha_tc;

    float raw[S];
    #pragma unroll
    for (int i = 0; i < S; i++) {
        int h = dir ? i : line;
        int w = dir ? line : i;
        int off = (c * S + h) * S + w;
        raw[i] = fmaxf(base[off] + tc[off] * tv, EPS_C);
    }
    // 3-tap replicate-padded smoothing along the solve dimension, times dt/DX^2
    float dt = dir ? DT_C : (DT_C * 0.5f);
    float cf[S];
    #pragma unroll
    for (int i = 0; i < S; i++) {
        float lm = raw[i == 0 ? 0 : i - 1];
        float rm = raw[i == S - 1 ? S - 1 : i + 1];
        cf[i] = (lm + raw[i] + rm) * (1.0f / 3.0f) * dt;
    }
    float* outp = dir ? g_py : g_px;
    float* outq = dir ? g_qy : g_qx;
    long ob = ((long)(t * CCH + c) * S + line) * S;
    float cp = 0.0f;
    #pragma unroll
    for (int i = 0; i < S; i++) {
        float b = 1.0f + 2.0f * cf[i];
        if (i == 0 || i == S - 1) b = 1.0f + cf[i];
        float a = -cf[i];
        float denom = b - a * cp + EPS_C;     // matches reference (+EPS every step)
        float p = 1.0f / denom;
        float q = a * p;                      // also equals cstar_i (a == c)
        cp = q;
        outp[ob + i] = p;
        outq[ob + i] = q;
    }
}

// One tridiagonal sweep of 32 independent systems (lane = batch) for one line.
// Coefficients via *broadcast* LDS.128 from per-line packed tables (all lanes
// same 16B -> 1 wavefront, 4 coefficients). asm volatile pins each load at
// its use site so ptxas cannot hoist vectors live and spill r[] (R2 failure
// mode, fixed by pinning since R3). paddr/qaddr = shared-space byte addresses
// of this line's p[32] / q[32] tables (128B-aligned).
template<bool COL, bool IN_SMEM, bool OUT_SMEM>
__device__ __forceinline__ void solve32(float* __restrict__ tile, float (&r)[S],
                                        unsigned paddr, unsigned qaddr,
                                        int line, int lane, float scale) {
    float prev = 0.0f;
    #pragma unroll
    for (int j = 0; j < 8; j++) {
        float p0, p1, p2, p3, q0, q1, q2, q3;
        asm volatile("ld.shared.v4.f32 {%0,%1,%2,%3},[%4];"
                     : "=f"(p0), "=f"(p1), "=f"(p2), "=f"(p3)
                     : "r"(paddr + 16u * j));
        asm volatile("ld.shared.v4.f32 {%0,%1,%2,%3},[%4];"
                     : "=f"(q0), "=f"(q1), "=f"(q2), "=f"(q3)
                     : "r"(qaddr + 16u * j));
        int i0 = 4 * j;
        #pragma unroll
        for (int e = 0; e < 4; e++) {
            int i = i0 + e;
            float p = e == 0 ? p0 : e == 1 ? p1 : e == 2 ? p2 : p3;
            float q = e == 0 ? q0 : e == 1 ? q1 : e == 2 ? q2 : q3;
            float d;
            if (IN_SMEM) {
                int el = COL ? (i * S + line) : (line * S + i);
                d = tile[el * 33 + lane];
            } else d = r[i];
            prev = fmaf(-q, prev, d * p);     // (d - a*prev)/denom
            r[i] = prev;
        }
    }
    float x = r[S - 1];                        // cstar[N-1] irrelevant (x_N = 0)
    r[S - 1] = x * scale;
    if (OUT_SMEM) {
        int el = COL ? ((S - 1) * S + line) : (line * S + (S - 1));
        tile[el * 33 + lane] = x * scale;
    }
    #pragma unroll
    for (int j = 7; j >= 0; j--) {
        float q0, q1, q2, q3;                  // q-only reload: 8 loads not 16
        asm volatile("ld.shared.v4.f32 {%0,%1,%2,%3},[%4];"
                     : "=f"(q0), "=f"(q1), "=f"(q2), "=f"(q3)
                     : "r"(qaddr + 16u * j));
        #pragma unroll
        for (int e = 3; e >= 0; e--) {
            int i = 4 * j + e;
            if (i == S - 1) continue;          // seed already placed
            float q = e == 0 ? q0 : e == 1 ? q1 : e == 2 ? q2 : q3;
            x = fmaf(-q, x, r[i]);             // cstar_i == q_i
            r[i] = x * scale;
            if (OUT_SMEM) {
                int el = COL ? (i * S + line) : (line * S + i);
                tile[el * 33 + lane] = x * scale;
            }
        }
    }
}

// Dynamic smem: [ spx | sqx | spy | sqy : 4096 floats each | tile: 33792 f ]
#define COEF_F_PER_TBL (NSTEPS * S * S)           // 4096 floats = 16KB per table
#define SMEM_BYTES (4 * COEF_F_PER_TBL * 4 + S * S * 33 * 4)   // 200704 B

__global__ void __launch_bounds__(1024, 1)
adi_kernel(const float* __restrict__ U, const float* __restrict__ coupling,
           float* __restrict__ Out) {
    extern __shared__ float smem[];
    float* spx  = smem;
    float* sqx  = spx + COEF_F_PER_TBL;
    float* spy  = sqx + COEF_F_PER_TBL;
    float* sqy  = spy + COEF_F_PER_TBL;
    float* tile = sqy + COEF_F_PER_TBL;

    int c    = blockIdx.x % CCH;
    int g    = blockIdx.x / CCH;
    int warp = threadIdx.x >> 5;
    int lane = threadIdx.x & 31;
    int tid  = threadIdx.x;

    // Stage this channel's packed tables (4 arrays x 16KB) with float4 copies.
    {
        const float4* src[4] = {(const float4*)g_px, (const float4*)g_qx,
                                (const float4*)g_py, (const float4*)g_qy};
        float4* dst[4] = {(float4*)spx, (float4*)sqx, (float4*)spy, (float4*)sqy};
        #pragma unroll
        for (int k = tid; k < 4096; k += 1024) {
            int a  = k >> 10;                  // which table
            int j  = k & 1023;                 // f4 index within table
            int t  = j >> 8;                   // 256 f4 per (step, channel)
            int jj = j & 255;
            dst[a][t * 256 + jj] = src[a][(t * CCH + c) * 256 + jj];
        }
    }

    unsigned bpx = (unsigned)__cvta_generic_to_shared(spx);
    unsigned bqx = (unsigned)__cvta_generic_to_shared(sqx);
    unsigned bpy = (unsigned)__cvta_generic_to_shared(spy);
    unsigned bqy = (unsigned)__cvta_generic_to_shared(sqy);

    size_t base = ((size_t)g * S) * (CCH * S * S) + (size_t)c * (S * S);
    const float* ub = U + base + (size_t)warp * (CCH * S * S);  // batch = g*32+warp

    // Coalesced load (128B/line) -> conflict-free STS thanks to the 33-pad.
    #pragma unroll
    for (int k = 0; k < S; k++)
        tile[(k * S + lane) * 33 + warp] = __ldg(ub + k * S + lane);

    float scal = coupling[c * CCH + c];       // einsum 'cc,bchw->bchw' = diag scale
    __syncthreads();

    float r[S];
    #pragma unroll 1
    for (int t = 0; t < NSTEPS; t++) {
        unsigned off = (unsigned)((t * S + warp) * S) * 4u;   // 128B per line table
        unsigned pax = bpx + off, qax = bqx + off;
        unsigned pay = bpy + off, qay = bqy + off;

        // x half-step #1: rows. Input comes from registers for t>0 (fused with
        // previous step's x2 output, same warp/lane/addresses -> no barrier).
        if (t == 0) solve32<false, true,  true>(tile, r, pax, qax, warp, lane, 1.0f);
        else        solve32<false, false, true>(tile, r, pax, qax, warp, lane, 1.0f);
        __syncthreads();

        // y full step: columns (r reused as scratch; rows already flushed).
        solve32<true, true, true>(tile, r, pay, qay, warp, lane, 1.0f);
        __syncthreads();

        // x half-step #2: rows, with channel coupling folded into the output.
        // For t<3 keep the result in registers only (next x1 consumes it).
        if (t == NSTEPS - 1) solve32<false, true, true >(tile, r, pax, qax, warp, lane, scal);
        else                 solve32<false, true, false>(tile, r, pax, qax, warp, lane, scal);
        if (t == NSTEPS - 1) __syncthreads();
    }

    float* ob = Out + base + (size_t)warp * (CCH * S * S);
    #pragma unroll
    for (int k = 0; k < S; k++)
        ob[k * S + lane] = tile[(k * S + lane) * 33 + warp];
}

extern "C" void kernel_launch(void* const* d_in, const int* in_sizes, int n_in,
                              void* d_out, int out_size) {
    (void)n_in; (void)out_size;
    const float* u   = (const float*)d_in[0];
    const float* ab  = (const float*)d_in[1];
    const float* bb  = (const float*)d_in[2];
    const float* atc = (const float*)d_in[3];
    const float* btc = (const float*)d_in[4];
    const float* cc  = (const float*)d_in[5];
    int B = in_sizes[0] / (CCH * S * S);      // 16384

    cudaFuncSetAttribute(adi_kernel, cudaFuncAttributeMaxDynamicSharedMemorySize,
                         SMEM_BYTES);

    precompute_kernel<<<3, 256>>>(ab, bb, atc, btc);   // 768 lines, trivial
    adi_kernel<<<(B / S) * CCH, 1024, SMEM_BYTES>>>(u, cc, (float*)d_out);
}